// round 3
// baseline (speedup 1.0000x reference)
#include <cuda_runtime.h>
#include <stdint.h>

// Problem constants (from reference_code)
#define B_DIM    16
#define C_DIM    23
#define T_DIM    120200
#define P_DIM    1000
#define PS_DIM   200
#define STRIDE_  150
#define ACTUAL_  801           // min((T-PS)/STRIDE + 1, MAX_PATCHES)

#define BC_DIM   (B_DIM * C_DIM)                 // 368
#define V4       (PS_DIM / 4)                    // 50 float4 per patch
#define PATCH_V4 (BC_DIM * P_DIM * V4)           // 18,400,000 float4 outputs
#define MASK_N   (BC_DIM * P_DIM)                // 368,000
#define TOTAL_T  (PATCH_V4 + MASK_N)             // 18,768,000 threads

// Fused kernel:
//   tid < PATCH_V4      : one float4 (16B) of patches output
//   tid >= PATCH_V4     : one float of mask output
//
// patches[bc, p, i] = x[bc, 150*p + i]  (p < 801), else 0
// Output writes: 16B aligned, fully coalesced.
// Input reads: offset = bc*120200 + 150*p + 4*v.
//   120200 % 4 == 0, so alignment mod 4 floats = (150*p) % 4 = 2*(p&1):
//   even p -> 16B aligned (one float4 load); odd p -> 8B aligned (two float2s).
__global__ void __launch_bounds__(256) to_patches_fused_kernel(
    const float* __restrict__ x, float* __restrict__ out)
{
    int tid = blockIdx.x * blockDim.x + threadIdx.x;
    if (tid >= TOTAL_T) return;

    if (tid < PATCH_V4) {
        int v    = tid % V4;          // float4 index within patch [0,50)
        int rest = tid / V4;
        int p    = rest % P_DIM;      // patch index [0,1000)
        int bc   = rest / P_DIM;      // fused (b,c) [0,368)

        float4 val;
        if (p < ACTUAL_) {
            const float* src = x + (size_t)bc * T_DIM + p * STRIDE_ + v * 4;
            if ((p & 1) == 0) {
                val = *reinterpret_cast<const float4*>(src);
            } else {
                float2 a = *reinterpret_cast<const float2*>(src);
                float2 b = *reinterpret_cast<const float2*>(src + 2);
                val = make_float4(a.x, a.y, b.x, b.y);
            }
        } else {
            val = make_float4(0.0f, 0.0f, 0.0f, 0.0f);
        }
        reinterpret_cast<float4*>(out)[tid] = val;
    } else {
        // mask region: starts at element PATCH_V4*4 of out
        int m = tid - PATCH_V4;       // [0, MASK_N)
        int p = m % P_DIM;
        out[(size_t)PATCH_V4 * 4 + m] = (p < ACTUAL_) ? 1.0f : 0.0f;
    }
}

extern "C" void kernel_launch(void* const* d_in, const int* in_sizes, int n_in,
                              void* d_out, int out_size)
{
    const float* x   = (const float*)d_in[0];
    float*       out = (float*)d_out;

    int threads = 256;
    int blocks  = (TOTAL_T + threads - 1) / threads;   // 73,313
    to_patches_fused_kernel<<<blocks, threads>>>(x, out);
}

// round 4
// speedup vs baseline: 1.0492x; 1.0492x over previous
#include <cuda_runtime.h>
#include <stdint.h>

// Problem constants (from reference_code)
#define B_DIM    16
#define C_DIM    23
#define T_DIM    120200
#define P_DIM    1000
#define PS_DIM   200
#define STRIDE_  150
#define ACTUAL_  801           // min((T-PS)/STRIDE + 1, MAX_PATCHES)

#define BC_DIM   (B_DIM * C_DIM)                 // 368
#define V4       (PS_DIM / 4)                    // 50 float4 per patch
#define PATCH_V4 (BC_DIM * P_DIM * V4)           // 18,400,000 float4 outputs
#define HALF_V4  (PATCH_V4 / 2)                  // 9,200,000
#define MASK_N   (BC_DIM * P_DIM)                // 368,000
#define TOTAL_T  (HALF_V4 + MASK_N)              // 9,568,000 threads

// Streaming (evict-first) stores: keep the 296MB write stream out of L2 so the
// read-window overlap (50/200 floats re-read by the next patch) stays resident.
__device__ __forceinline__ void stcs4(float4* p, float4 v) {
    asm volatile("st.global.cs.v4.f32 [%0], {%1,%2,%3,%4};"
                 :: "l"(p), "f"(v.x), "f"(v.y), "f"(v.z), "f"(v.w) : "memory");
}
__device__ __forceinline__ void stcs1(float* p, float v) {
    asm volatile("st.global.cs.f32 [%0], %1;" :: "l"(p), "f"(v) : "memory");
}

// Compute one float4 of the patches output for flat float4-index `o`.
__device__ __forceinline__ float4 patch_val(const float* __restrict__ x, int o) {
    int v    = o % V4;          // float4 index within patch [0,50)
    int rest = o / V4;
    int p    = rest % P_DIM;    // patch index [0,1000)
    int bc   = rest / P_DIM;    // fused (b,c) [0,368)

    if (p >= ACTUAL_) return make_float4(0.f, 0.f, 0.f, 0.f);

    // src offset = bc*120200 + 150*p + 4*v ; 16B-aligned iff p even.
    const float* src = x + (size_t)bc * T_DIM + p * STRIDE_ + v * 4;
    if ((p & 1) == 0) {
        return *reinterpret_cast<const float4*>(src);
    } else {
        float2 a = *reinterpret_cast<const float2*>(src);
        float2 b = *reinterpret_cast<const float2*>(src + 2);
        return make_float4(a.x, a.y, b.x, b.y);
    }
}

// Fused kernel, 2 independent float4s per thread (MLP=2):
//   tid < HALF_V4 : patches float4 at tid and tid + HALF_V4
//   else          : one mask float
__global__ void __launch_bounds__(256) to_patches_fused_kernel(
    const float* __restrict__ x, float* __restrict__ out)
{
    int tid = blockIdx.x * blockDim.x + threadIdx.x;
    if (tid >= TOTAL_T) return;

    if (tid < HALF_V4) {
        int o0 = tid;
        int o1 = tid + HALF_V4;
        // Two independent load->store chains; compiler batches both LDGs first.
        float4 v0 = patch_val(x, o0);
        float4 v1 = patch_val(x, o1);
        stcs4(reinterpret_cast<float4*>(out) + o0, v0);
        stcs4(reinterpret_cast<float4*>(out) + o1, v1);
    } else {
        int m = tid - HALF_V4;        // [0, MASK_N)
        int p = m % P_DIM;
        stcs1(out + (size_t)PATCH_V4 * 4 + m, (p < ACTUAL_) ? 1.0f : 0.0f);
    }
}

extern "C" void kernel_launch(void* const* d_in, const int* in_sizes, int n_in,
                              void* d_out, int out_size)
{
    const float* x   = (const float*)d_in[0];
    float*       out = (float*)d_out;

    int threads = 256;
    int blocks  = (TOTAL_T + threads - 1) / threads;   // 37,375
    to_patches_fused_kernel<<<blocks, threads>>>(x, out);
}